// round 10
// baseline (speedup 1.0000x reference)
#include <cuda_runtime.h>
#include <cuda_fp16.h>
#include <math.h>
#include <stdint.h>

// Problem constants
#define NN 16
#define CC 256
#define HH 64
#define WW 64
#define HW (HH * WW)        // 4096
#define K2 9
#define BN_EPS 1e-5f

// Scratch (device globals; no allocation allowed)
__device__ float g_h[NN * CC * HW];                    // conv1 out (BN+PReLU)
__device__ float g_kern[NN * K2 * HW];                 // dyn kernel [N,9,H*W]
__device__ __align__(16) __half g_wth[K2 * CC * CC];   // W1 hi fp16 [tap][co][ci]
__device__ __align__(16) __half g_wtl[K2 * CC * CC];   // W1 lo fp16
__device__ __align__(16) __half g_yth[NN * HW * CC];   // y fp16 K-major [n][pix][ci]

// ===========================================================================
// mma.sync / ldmatrix / cp.async helpers (baseline PTX, valid at compute_103)
// ===========================================================================
__device__ __forceinline__ uint32_t smem_u32(const void* p) {
    uint32_t a;
    asm("{ .reg .u64 t; cvta.to.shared.u64 t, %1; cvt.u32.u64 %0, t; }"
        : "=r"(a) : "l"(p));
    return a;
}
__device__ __forceinline__ void ldsm4(uint32_t& r0, uint32_t& r1,
                                      uint32_t& r2, uint32_t& r3, uint32_t addr) {
    asm volatile("ldmatrix.sync.aligned.m8n8.x4.shared.b16 {%0,%1,%2,%3}, [%4];"
                 : "=r"(r0), "=r"(r1), "=r"(r2), "=r"(r3) : "r"(addr));
}
__device__ __forceinline__ void mma_f16(float* c, const uint32_t* a, const uint32_t* b) {
    asm volatile("mma.sync.aligned.m16n8k16.row.col.f32.f16.f16.f32 "
                 "{%0,%1,%2,%3}, {%4,%5,%6,%7}, {%8,%9}, {%0,%1,%2,%3};"
                 : "+f"(c[0]), "+f"(c[1]), "+f"(c[2]), "+f"(c[3])
                 : "r"(a[0]), "r"(a[1]), "r"(a[2]), "r"(a[3]), "r"(b[0]), "r"(b[1]));
}
__device__ __forceinline__ void cp16(uint32_t dst, const void* src, int srcsz) {
    asm volatile("cp.async.cg.shared.global [%0], [%1], 16, %2;"
                 :: "r"(dst), "l"(src), "r"(srcsz) : "memory");
}
#define CP_COMMIT() asm volatile("cp.async.commit_group;" ::: "memory")
#define CP_WAIT1()  asm volatile("cp.async.wait_group 1;" ::: "memory")
#define CP_WAIT0()  asm volatile("cp.async.wait_group 0;" ::: "memory")

// ===========================================================================
// Prep A: W1 [co][ci][3][3] fp32 -> wt hi/lo fp16 [tap][co][ci]
// ===========================================================================
__global__ __launch_bounds__(256)
void prep_weights(const float* __restrict__ W1)
{
    int idx = blockIdx.x * 256 + threadIdx.x;     // over 9*256*256
    if (idx >= K2 * CC * CC) return;
    int k   = idx >> 16;
    int rem = idx & 0xFFFF;
    int co  = rem >> 8;
    int ci  = rem & 255;
    float v = W1[((size_t)co * CC + ci) * 9 + k];
    __half h = __float2half(v);
    __half l = __float2half(v - __half2float(h));
    g_wth[idx] = h;
    g_wtl[idx] = l;
}

// ===========================================================================
// Prep B: transpose y [n][ci][p] fp32 -> y fp16 [n][p][ci]
// ===========================================================================
__global__ __launch_bounds__(256)
void prep_y_transpose(const float* __restrict__ y)
{
    __shared__ float s[32][33];
    const int n  = blockIdx.z;
    const int p0 = blockIdx.x * 32;
    const int c0 = blockIdx.y * 32;
    const int tx = threadIdx.x;
    const int j  = tx & 31;
    const int i  = tx >> 5;            // 0..7

#pragma unroll
    for (int it = 0; it < 4; it++) {
        int ci = c0 + i + it * 8;
        s[i + it * 8][j] = y[((size_t)n * CC + ci) * HW + p0 + j];
    }
    __syncthreads();
#pragma unroll
    for (int it = 0; it < 4; it++) {
        int pl = i + it * 8;
        g_yth[((size_t)n * HW + p0 + pl) * CC + c0 + j] = __float2half(s[j][pl]);
    }
}

// ===========================================================================
// Kernel 1: conv3x3 as 9-tap GEMM on mma.sync (fp16 2-term split, fp32 acc).
// out = (Wh + Wl) * fp16(y): weights exact to ~22 bits, only y rounded.
// CTA tile: M=128 co x N=256 pix. 8 warps, warp tile 64x64.
// ci-chunk outer / tap inner; B staged once per chunk as 6x66 halo region
// (hi only now); A (hi+lo) double-buffered across taps via cp.async.
// ===========================================================================
#define LDB 144                         // bytes per padded smem row
#define A_HL  (128 * LDB)               // lo offset inside an A buffer (18432)
#define A_BUF (2 * 128 * LDB)           // one A buffer hi+lo (36864)
#define OFF_A 0
#define OFF_BH (2 * A_BUF)              // 73728
#define EXTR 396                        // 6*66 extended pixel rows
#define CONV_SMEM (OFF_BH + EXTR * LDB) // 130752

__global__ __launch_bounds__(256, 1)
void conv3x3_mma(const float* __restrict__ g1,
                 const float* __restrict__ b1,
                 const float* __restrict__ m1,
                 const float* __restrict__ v1,
                 const float* __restrict__ a1)
{
    extern __shared__ char sb[];
    const uint32_t sb32 = smem_u32(sb);

    const int tid  = threadIdx.x;
    const int wid  = tid >> 5;
    const int lane = tid & 31;
    const int wm   = wid >> 2;          // 0..1  (co 64-block)
    const int wn   = wid & 3;           // 0..3  (pix 64-block)
    const int P0   = blockIdx.x * 256;
    const int hh0  = P0 >> 6;           // first image row of this tile
    const int cob  = blockIdx.y * 128;
    const int n    = blockIdx.z;

    const int quad = lane >> 3;         // 0..3
    const int lrow = lane & 7;

    // ldmatrix lane-address components (verified fragment mapping from R8)
    const int armBase = wm * 64 + lrow + ((quad & 1) << 3);
    const int akAdd   = (quad >> 1) << 3;
    const int bnBase  = wn * 64 + lrow + ((quad >> 1) << 3);
    const int bkAdd   = (quad & 1) << 3;

    float acc[4][8][4];
#pragma unroll
    for (int mt = 0; mt < 4; mt++)
#pragma unroll
        for (int nt = 0; nt < 8; nt++)
#pragma unroll
            for (int i = 0; i < 4; i++) acc[mt][nt][i] = 0.f;

    for (int ci0 = 0; ci0 < CC; ci0 += 64) {
        __syncthreads();   // all compute on previous chunk's B/A done

        // ---- stage extended B region (hi only), zeros at image border ------
        for (int i = tid; i < EXTR * 8; i += 256) {
            int r = i >> 3, q = i & 7;
            int er = r / 66, ec = r - er * 66;
            int ih = hh0 - 1 + er;
            int iw = ec - 1;
            bool valid = ((unsigned)ih < (unsigned)HH) && ((unsigned)iw < (unsigned)WW);
            size_t srow = valid ? (((size_t)n * HW + (ih << 6) + iw) * CC + ci0 + q * 8)
                                : 0;
            int sz = valid ? 16 : 0;
            cp16(sb32 + OFF_BH + (uint32_t)(r * LDB + q * 16), g_yth + srow, sz);
        }
        // ---- stage A for tap 0 into buffer 0 -------------------------------
        {
            const __half* srcH = g_wth + ((size_t)cob << 8) + ci0;
            const __half* srcL = g_wtl + ((size_t)cob << 8) + ci0;
            for (int i = tid; i < 1024; i += 256) {
                int r = i >> 3, q = i & 7;
                uint32_t d = (uint32_t)(r * LDB + q * 16);
                cp16(sb32 + OFF_A + d,        srcH + r * 256 + q * 8, 16);
                cp16(sb32 + OFF_A + A_HL + d, srcL + r * 256 + q * 8, 16);
            }
        }
        CP_COMMIT();

        for (int tap = 0; tap < 9; tap++) {
            __syncthreads();   // protect A buffer (tap+1)&1 from overwrite
            if (tap < 8) {
                const int tn = tap + 1;
                const uint32_t bo = OFF_A + (uint32_t)(tn & 1) * A_BUF;
                const __half* srcH = g_wth + ((size_t)tn << 16) +
                                     ((size_t)cob << 8) + ci0;
                const __half* srcL = g_wtl + ((size_t)tn << 16) +
                                     ((size_t)cob << 8) + ci0;
                for (int i = tid; i < 1024; i += 256) {
                    int r = i >> 3, q = i & 7;
                    uint32_t d = bo + (uint32_t)(r * LDB + q * 16);
                    cp16(sb32 + d,        srcH + r * 256 + q * 8, 16);
                    cp16(sb32 + d + A_HL, srcL + r * 256 + q * 8, 16);
                }
                CP_COMMIT();
                CP_WAIT1();          // current tap's A (+B on tap 0) complete
            } else {
                CP_WAIT0();
            }
            __syncthreads();

            // extended-row indices for this tap (per lane, per n-tile pair)
            const int dr = tap / 3 - 1;
            const int ds = tap - (tap / 3) * 3 - 1;
            int eb[4];
#pragma unroll
            for (int ntp = 0; ntp < 4; ntp++) {
                int rl = bnBase + ntp * 16;
                eb[ntp] = ((rl >> 6) + dr + 1) * 66 + (rl & 63) + ds + 1;
            }
            const uint32_t abuf = sb32 + OFF_A + (uint32_t)(tap & 1) * A_BUF;

#pragma unroll
            for (int kk = 0; kk < 4; kk++) {
                const int k0 = kk * 16;
                uint32_t ah[4][4], al[4][4], bh[8][2];
#pragma unroll
                for (int mt = 0; mt < 4; mt++) {
                    uint32_t aoff = (uint32_t)((armBase + mt * 16) * LDB +
                                               (k0 + akAdd) * 2);
                    ldsm4(ah[mt][0], ah[mt][1], ah[mt][2], ah[mt][3], abuf + aoff);
                    ldsm4(al[mt][0], al[mt][1], al[mt][2], al[mt][3],
                          abuf + A_HL + aoff);
                }
#pragma unroll
                for (int ntp = 0; ntp < 4; ntp++) {
                    uint32_t boff = (uint32_t)(eb[ntp] * LDB + (k0 + bkAdd) * 2);
                    ldsm4(bh[2 * ntp][0], bh[2 * ntp][1],
                          bh[2 * ntp + 1][0], bh[2 * ntp + 1][1],
                          sb32 + OFF_BH + boff);
                }
#pragma unroll
                for (int mt = 0; mt < 4; mt++) {
#pragma unroll
                    for (int nt = 0; nt < 8; nt++) {
                        mma_f16(acc[mt][nt], ah[mt], bh[nt]);   // hi * y
                        mma_f16(acc[mt][nt], al[mt], bh[nt]);   // lo * y
                    }
                }
            }
        }
    }

    // ---- epilogue: BN + PReLU, store float2 pairs
    const float alpha = a1[0];
#pragma unroll
    for (int mt = 0; mt < 4; mt++) {
        int r0  = wm * 64 + mt * 16 + (lane >> 2);
        int co0 = cob + r0;
        int co1 = co0 + 8;
        float sc0 = g1[co0] * rsqrtf(v1[co0] + BN_EPS);
        float sh0 = b1[co0] - m1[co0] * sc0;
        float sc1 = g1[co1] * rsqrtf(v1[co1] + BN_EPS);
        float sh1 = b1[co1] - m1[co1] * sc1;
        float* base0 = g_h + ((size_t)n * CC + co0) * HW;
        float* base1 = g_h + ((size_t)n * CC + co1) * HW;
#pragma unroll
        for (int nt = 0; nt < 8; nt++) {
            int col = P0 + wn * 64 + nt * 8 + 2 * (lane & 3);
            float v0 = acc[mt][nt][0] * sc0 + sh0;
            float v1_ = acc[mt][nt][1] * sc0 + sh0;
            float v2 = acc[mt][nt][2] * sc1 + sh1;
            float v3 = acc[mt][nt][3] * sc1 + sh1;
            float2 o0, o1;
            o0.x = (v0 >= 0.f) ? v0 : alpha * v0;
            o0.y = (v1_ >= 0.f) ? v1_ : alpha * v1_;
            o1.x = (v2 >= 0.f) ? v2 : alpha * v2;
            o1.y = (v3 >= 0.f) ? v3 : alpha * v3;
            *(float2*)(base0 + col) = o0;
            *(float2*)(base1 + col) = o1;
        }
    }
}

// ===========================================================================
// Kernel 2: 1x1 conv (C->9) + BN + PReLU -> g_kern [N,9,H*W]
// Split-K: 512 threads, 2 threads per pixel (128 ci each), smem combine.
// ===========================================================================
__global__ __launch_bounds__(512)
void conv1x1_bn_prelu(const float* __restrict__ W2,
                      const float* __restrict__ g2,
                      const float* __restrict__ b2,
                      const float* __restrict__ m2,
                      const float* __restrict__ v2,
                      const float* __restrict__ a2)
{
    __shared__ float w2s[K2][CC];
    __shared__ float part[256][K2];
    const int tx   = threadIdx.x;
    const int half = tx >> 8;          // 0 or 1 (ci half)
    const int t    = tx & 255;         // pixel slot
    for (int i = tx; i < K2 * CC; i += 512) {
        int k  = i / CC;
        int ci = i - k * CC;
        w2s[k][ci] = W2[k * CC + ci];
    }
    __syncthreads();

    int pix = blockIdx.x * 256 + t;
    int n   = pix / HW;
    int hw  = pix - n * HW;

    float acc[K2];
#pragma unroll
    for (int k = 0; k < K2; k++) acc[k] = 0.f;

    const int cbase = half * 128;
    const float* hp = g_h + (size_t)n * CC * HW + (size_t)cbase * HW + hw;
#pragma unroll 8
    for (int ci = 0; ci < 128; ci++) {
        float v = hp[(size_t)ci * HW];
#pragma unroll
        for (int k = 0; k < K2; k++)
            acc[k] = fmaf(v, w2s[k][cbase + ci], acc[k]);
    }

    if (half == 1) {
#pragma unroll
        for (int k = 0; k < K2; k++) part[t][k] = acc[k];
    }
    __syncthreads();
    if (half == 0) {
        const float alpha = a2[0];
#pragma unroll
        for (int k = 0; k < K2; k++) {
            float sc = g2[k] * rsqrtf(v2[k] + BN_EPS);
            float sh = b2[k] - m2[k] * sc;
            float v  = (acc[k] + part[t][k]) * sc + sh;
            v = (v >= 0.f) ? v : alpha * v;
            g_kern[((size_t)n * K2 + k) * HW + hw] = v;
        }
    }
}

// ===========================================================================
// Kernel 3: dynamic filter application with torch's ROW-MAJOR reshape scramble
// ===========================================================================
#define G_P 4
#define SLAB 2304
#define SLABP 2305

__global__ __launch_bounds__(256)
void apply_dynamic_kernel(const float* __restrict__ x,
                          float* __restrict__ out)
{
    __shared__ float sA[G_P * SLABP];
    __shared__ float sk[G_P][K2];

    const int tid = threadIdx.x;
    const int P0  = blockIdx.x * G_P;
    const int n   = blockIdx.y;

    if (tid < G_P * K2) {
        int p = tid / K2;
        int k = tid - p * K2;
        sk[p][k] = g_kern[((size_t)n * K2 + k) * HW + P0 + p];
    }

    const float* xn = x + (size_t)n * CC * HW;
    const int base = P0 * SLAB;

    for (int t = tid; t < G_P * SLAB; t += 256) {
        int flat = base + t;
        int w2 = flat & 63;
        int j  = flat >> 6;
        int h2 = j & 63;
        int q  = j >> 6;             // c2*9 + k2
        int k2 = q % 9;
        int c2 = q / 9;
        int r  = k2 / 3;
        int s  = k2 - r * 3;
        int ih = h2 + r - 1;
        int iw = w2 + s - 1;
        float v = 0.f;
        if (ih >= 0 && ih < HH && iw >= 0 && iw < WW)
            v = xn[c2 * HW + ih * WW + iw];
        int slab = t / SLAB;
        int off  = t - slab * SLAB;
        sA[slab * SLABP + off] = v;
    }
    __syncthreads();

    const int c = tid;
    float res[G_P];
#pragma unroll
    for (int p = 0; p < G_P; p++) {
        const float* a = sA + p * SLABP + c * K2;
        float acc = 0.f;
#pragma unroll
        for (int k = 0; k < K2; k++)
            acc = fmaf(a[k], sk[p][k], acc);
        res[p] = acc;
    }

    float* dst = out + ((size_t)n * CC + c) * HW + P0;
#pragma unroll
    for (int p = 0; p < G_P; p++) dst[p] = res[p];
}

// ===========================================================================
extern "C" void kernel_launch(void* const* d_in, const int* in_sizes, int n_in,
                              void* d_out, int out_size)
{
    const float* x  = (const float*)d_in[0];
    const float* y  = (const float*)d_in[1];
    const float* W1 = (const float*)d_in[2];
    const float* g1 = (const float*)d_in[3];
    const float* b1 = (const float*)d_in[4];
    const float* m1 = (const float*)d_in[5];
    const float* v1 = (const float*)d_in[6];
    const float* a1 = (const float*)d_in[7];
    const float* W2 = (const float*)d_in[8];
    const float* g2 = (const float*)d_in[9];
    const float* b2 = (const float*)d_in[10];
    const float* m2 = (const float*)d_in[11];
    const float* v2 = (const float*)d_in[12];
    const float* a2 = (const float*)d_in[13];
    float* out = (float*)d_out;

    static bool attr_set = false;
    if (!attr_set) {
        cudaFuncSetAttribute(conv3x3_mma,
                             cudaFuncAttributeMaxDynamicSharedMemorySize,
                             CONV_SMEM);
        attr_set = true;
    }

    // prep: weight reshape + y transpose to fp16
    prep_weights<<<(K2 * CC * CC + 255) / 256, 256>>>(W1);
    {
        dim3 g(HW / 32, CC / 32, NN);    // (128, 8, 16)
        prep_y_transpose<<<g, 256>>>(y);
    }
    // conv1 on mma.sync tensor cores (fp16 2-term split, pipelined)
    {
        dim3 g(HW / 256, CC / 128, NN);  // (16, 2, 16) = 512 CTAs
        conv3x3_mma<<<g, 256, CONV_SMEM>>>(g1, b1, m1, v1, a1);
    }
    // 1x1 conv (split-K, 512 threads)
    conv1x1_bn_prelu<<<(NN * HW) / 256, 512>>>(W2, g2, b2, m2, v2, a2);
    // dynamic filter application
    {
        dim3 g(HW / G_P, NN);            // (1024, 16)
        apply_dynamic_kernel<<<g, 256>>>(x, out);
    }
}

// round 11
// speedup vs baseline: 1.3051x; 1.3051x over previous
#include <cuda_runtime.h>
#include <cuda_bf16.h>
#include <math.h>
#include <stdint.h>

// Problem constants
#define NN 16
#define CC 256
#define HH 64
#define WW 64
#define HW (HH * WW)        // 4096
#define K2 9
#define BN_EPS 1e-5f

// Scratch (device globals; no allocation allowed)
__device__ float g_h[NN * CC * HW];                         // conv1 out (BN+PReLU)
__device__ float g_kern[NN * K2 * HW];                      // dyn kernel [N,9,H*W]
__device__ __align__(16) __nv_bfloat16 g_wth[K2 * CC * CC]; // W1 hi [tap][co][ci]
__device__ __align__(16) __nv_bfloat16 g_wtl[K2 * CC * CC]; // W1 lo
__device__ __align__(16) __nv_bfloat16 g_yth[NN * HW * CC]; // y hi K-major [n][pix][ci]
__device__ __align__(16) __nv_bfloat16 g_ytl[NN * HW * CC]; // y lo

// ===========================================================================
// mma.sync / ldmatrix / cp.async helpers (baseline PTX, valid at compute_103)
// ===========================================================================
__device__ __forceinline__ uint32_t smem_u32(const void* p) {
    uint32_t a;
    asm("{ .reg .u64 t; cvta.to.shared.u64 t, %1; cvt.u32.u64 %0, t; }"
        : "=r"(a) : "l"(p));
    return a;
}
__device__ __forceinline__ void ldsm4(uint32_t& r0, uint32_t& r1,
                                      uint32_t& r2, uint32_t& r3, uint32_t addr) {
    asm volatile("ldmatrix.sync.aligned.m8n8.x4.shared.b16 {%0,%1,%2,%3}, [%4];"
                 : "=r"(r0), "=r"(r1), "=r"(r2), "=r"(r3) : "r"(addr));
}
__device__ __forceinline__ void mma_bf16(float* c, const uint32_t* a, const uint32_t* b) {
    asm volatile("mma.sync.aligned.m16n8k16.row.col.f32.bf16.bf16.f32 "
                 "{%0,%1,%2,%3}, {%4,%5,%6,%7}, {%8,%9}, {%0,%1,%2,%3};"
                 : "+f"(c[0]), "+f"(c[1]), "+f"(c[2]), "+f"(c[3])
                 : "r"(a[0]), "r"(a[1]), "r"(a[2]), "r"(a[3]), "r"(b[0]), "r"(b[1]));
}
__device__ __forceinline__ void cp16(uint32_t dst, const void* src, int srcsz) {
    asm volatile("cp.async.cg.shared.global [%0], [%1], 16, %2;"
                 :: "r"(dst), "l"(src), "r"(srcsz) : "memory");
}
#define CP_COMMIT() asm volatile("cp.async.commit_group;" ::: "memory")
#define CP_WAIT1()  asm volatile("cp.async.wait_group 1;" ::: "memory")
#define CP_WAIT0()  asm volatile("cp.async.wait_group 0;" ::: "memory")

// ===========================================================================
// Prep A: W1 [co][ci][3][3] fp32 -> wt hi/lo bf16 [tap][co][ci]
// ===========================================================================
__global__ __launch_bounds__(256)
void prep_weights(const float* __restrict__ W1)
{
    int idx = blockIdx.x * 256 + threadIdx.x;     // over 9*256*256
    if (idx >= K2 * CC * CC) return;
    int k   = idx >> 16;
    int rem = idx & 0xFFFF;
    int co  = rem >> 8;
    int ci  = rem & 255;
    float v = W1[((size_t)co * CC + ci) * 9 + k];
    __nv_bfloat16 h = __float2bfloat16(v);
    __nv_bfloat16 l = __float2bfloat16(v - __bfloat162float(h));
    g_wth[idx] = h;
    g_wtl[idx] = l;
}

// ===========================================================================
// Prep B: transpose y [n][ci][p] fp32 -> yt hi/lo bf16 [n][p][ci]
// ===========================================================================
__global__ __launch_bounds__(256)
void prep_y_transpose(const float* __restrict__ y)
{
    __shared__ float s[32][33];
    const int n  = blockIdx.z;
    const int p0 = blockIdx.x * 32;
    const int c0 = blockIdx.y * 32;
    const int tx = threadIdx.x;
    const int j  = tx & 31;
    const int i  = tx >> 5;            // 0..7

#pragma unroll
    for (int it = 0; it < 4; it++) {
        int ci = c0 + i + it * 8;
        s[i + it * 8][j] = y[((size_t)n * CC + ci) * HW + p0 + j];
    }
    __syncthreads();
#pragma unroll
    for (int it = 0; it < 4; it++) {
        int pl = i + it * 8;
        float v = s[j][pl];
        __nv_bfloat16 h = __float2bfloat16(v);
        __nv_bfloat16 l = __float2bfloat16(v - __bfloat162float(h));
        size_t o = ((size_t)n * HW + p0 + pl) * CC + c0 + j;
        g_yth[o] = h;
        g_ytl[o] = l;
    }
}

// ===========================================================================
// Kernel 1: conv3x3 as 9-tap GEMM on mma.sync, bf16 hi/lo 3-MMA, fp32 acc.
// NEW GEOMETRY for 2 CTAs/SM: CTA tile M=128 co x N=128 pix (2 image rows),
// 8 warps at 64x32 each (acc = 64 regs). ci chunks of 32 (LDB=80: 8-row
// ldmatrix groups hit distinct 16B banks -> conflict-free).
// B staged once per chunk as a 4x66 halo region (hi+lo); A double-buffered
// across taps via cp.async. smem = 83200 B, regs <= 128 -> occupancy 2.
// ===========================================================================
#define LDB 80                          // bytes per padded smem row (32 ci)
#define A_HL  (128 * LDB)               // lo offset inside an A buffer (10240)
#define A_BUF (2 * A_HL)                // one A buffer hi+lo (20480)
#define OFF_A 0                         // two buffers: 0, A_BUF
#define OFF_BH (2 * A_BUF)              // 40960
#define EXTR 264                        // 4*66 extended pixel rows
#define OFF_BL (OFF_BH + EXTR * LDB)    // 62080
#define CONV_SMEM (OFF_BL + EXTR * LDB) // 83200

__global__ __launch_bounds__(256, 2)
void conv3x3_mma(const float* __restrict__ g1,
                 const float* __restrict__ b1,
                 const float* __restrict__ m1,
                 const float* __restrict__ v1,
                 const float* __restrict__ a1)
{
    extern __shared__ char sb[];
    const uint32_t sb32 = smem_u32(sb);

    const int tid  = threadIdx.x;
    const int wid  = tid >> 5;
    const int lane = tid & 31;
    const int wm   = wid >> 2;          // 0..1  (co 64-block)
    const int wn   = wid & 3;           // 0..3  (pix 32-block)
    const int P0   = blockIdx.x * 128;
    const int hh0  = P0 >> 6;           // first image row of this tile
    const int cob  = blockIdx.y * 128;
    const int n    = blockIdx.z;

    const int quad = lane >> 3;         // 0..3
    const int lrow = lane & 7;

    // ldmatrix lane-address components (fragment mapping verified in R8)
    const int armBase = wm * 64 + lrow + ((quad & 1) << 3);
    const int akAdd   = (quad >> 1) << 3;
    const int bnBase  = wn * 32 + lrow + ((quad >> 1) << 3);
    const int bkAdd   = (quad & 1) << 3;

    float acc[4][4][4];
#pragma unroll
    for (int mt = 0; mt < 4; mt++)
#pragma unroll
        for (int nt = 0; nt < 4; nt++)
#pragma unroll
            for (int i = 0; i < 4; i++) acc[mt][nt][i] = 0.f;

    for (int ci0 = 0; ci0 < CC; ci0 += 32) {
        __syncthreads();   // all compute on previous chunk's B/A done

        // ---- stage extended B region (hi+lo), zeros at image border --------
        for (int i = tid; i < EXTR * 4; i += 256) {
            int r = i >> 2, q = i & 3;
            int er = r / 66, ec = r - er * 66;
            int ih = hh0 - 1 + er;
            int iw = ec - 1;
            bool valid = ((unsigned)ih < (unsigned)HH) && ((unsigned)iw < (unsigned)WW);
            size_t srow = valid ? (((size_t)n * HW + (ih << 6) + iw) * CC + ci0 + q * 8)
                                : 0;
            int sz = valid ? 16 : 0;
            uint32_t d = (uint32_t)(r * LDB + q * 16);
            cp16(sb32 + OFF_BH + d, g_yth + srow, sz);
            cp16(sb32 + OFF_BL + d, g_ytl + srow, sz);
        }
        // ---- stage A for tap 0 into buffer 0 -------------------------------
        {
            const __nv_bfloat16* srcH = g_wth + ((size_t)cob << 8) + ci0;
            const __nv_bfloat16* srcL = g_wtl + ((size_t)cob << 8) + ci0;
            for (int i = tid; i < 512; i += 256) {
                int r = i >> 2, q = i & 3;
                uint32_t d = (uint32_t)(r * LDB + q * 16);
                cp16(sb32 + OFF_A + d,        srcH + r * 256 + q * 8, 16);
                cp16(sb32 + OFF_A + A_HL + d, srcL + r * 256 + q * 8, 16);
            }
        }
        CP_COMMIT();

        for (int tap = 0; tap < 9; tap++) {
            __syncthreads();   // protect A buffer (tap+1)&1 from overwrite
            if (tap < 8) {
                const int tn = tap + 1;
                const uint32_t bo = OFF_A + (uint32_t)(tn & 1) * A_BUF;
                const __nv_bfloat16* srcH = g_wth + ((size_t)tn << 16) +
                                            ((size_t)cob << 8) + ci0;
                const __nv_bfloat16* srcL = g_wtl + ((size_t)tn << 16) +
                                            ((size_t)cob << 8) + ci0;
                for (int i = tid; i < 512; i += 256) {
                    int r = i >> 2, q = i & 3;
                    uint32_t d = bo + (uint32_t)(r * LDB + q * 16);
                    cp16(sb32 + d,        srcH + r * 256 + q * 8, 16);
                    cp16(sb32 + d + A_HL, srcL + r * 256 + q * 8, 16);
                }
                CP_COMMIT();
                CP_WAIT1();          // current tap's A (+B on tap 0) complete
            } else {
                CP_WAIT0();
            }
            __syncthreads();

            // extended-row indices for this tap (per lane, per n-tile pair)
            const int dr = tap / 3 - 1;
            const int ds = tap - (tap / 3) * 3 - 1;
            int eb[2];
#pragma unroll
            for (int ntp = 0; ntp < 2; ntp++) {
                int rl = bnBase + ntp * 16;
                eb[ntp] = ((rl >> 6) + dr + 1) * 66 + (rl & 63) + ds + 1;
            }
            const uint32_t abuf = sb32 + OFF_A + (uint32_t)(tap & 1) * A_BUF;

#pragma unroll
            for (int kk = 0; kk < 2; kk++) {
                const int k0 = kk * 16;
                uint32_t ah[4][4], al[4][4], bh[4][2], bl[4][2];
#pragma unroll
                for (int mt = 0; mt < 4; mt++) {
                    uint32_t aoff = (uint32_t)((armBase + mt * 16) * LDB +
                                               (k0 + akAdd) * 2);
                    ldsm4(ah[mt][0], ah[mt][1], ah[mt][2], ah[mt][3], abuf + aoff);
                    ldsm4(al[mt][0], al[mt][1], al[mt][2], al[mt][3],
                          abuf + A_HL + aoff);
                }
#pragma unroll
                for (int ntp = 0; ntp < 2; ntp++) {
                    uint32_t boff = (uint32_t)(eb[ntp] * LDB + (k0 + bkAdd) * 2);
                    ldsm4(bh[2 * ntp][0], bh[2 * ntp][1],
                          bh[2 * ntp + 1][0], bh[2 * ntp + 1][1],
                          sb32 + OFF_BH + boff);
                    ldsm4(bl[2 * ntp][0], bl[2 * ntp][1],
                          bl[2 * ntp + 1][0], bl[2 * ntp + 1][1],
                          sb32 + OFF_BL + boff);
                }
#pragma unroll
                for (int mt = 0; mt < 4; mt++) {
#pragma unroll
                    for (int nt = 0; nt < 4; nt++) {
                        mma_bf16(acc[mt][nt], ah[mt], bh[nt]);   // hi*hi
                        mma_bf16(acc[mt][nt], ah[mt], bl[nt]);   // hi*lo
                        mma_bf16(acc[mt][nt], al[mt], bh[nt]);   // lo*hi
                    }
                }
            }
        }
    }

    // ---- epilogue: BN + PReLU, store float2 pairs
    const float alpha = a1[0];
#pragma unroll
    for (int mt = 0; mt < 4; mt++) {
        int r0  = wm * 64 + mt * 16 + (lane >> 2);
        int co0 = cob + r0;
        int co1 = co0 + 8;
        float sc0 = g1[co0] * rsqrtf(v1[co0] + BN_EPS);
        float sh0 = b1[co0] - m1[co0] * sc0;
        float sc1 = g1[co1] * rsqrtf(v1[co1] + BN_EPS);
        float sh1 = b1[co1] - m1[co1] * sc1;
        float* base0 = g_h + ((size_t)n * CC + co0) * HW;
        float* base1 = g_h + ((size_t)n * CC + co1) * HW;
#pragma unroll
        for (int nt = 0; nt < 4; nt++) {
            int col = P0 + wn * 32 + nt * 8 + 2 * (lane & 3);
            float v0 = acc[mt][nt][0] * sc0 + sh0;
            float v1_ = acc[mt][nt][1] * sc0 + sh0;
            float v2 = acc[mt][nt][2] * sc1 + sh1;
            float v3 = acc[mt][nt][3] * sc1 + sh1;
            float2 o0, o1;
            o0.x = (v0 >= 0.f) ? v0 : alpha * v0;
            o0.y = (v1_ >= 0.f) ? v1_ : alpha * v1_;
            o1.x = (v2 >= 0.f) ? v2 : alpha * v2;
            o1.y = (v3 >= 0.f) ? v3 : alpha * v3;
            *(float2*)(base0 + col) = o0;
            *(float2*)(base1 + col) = o1;
        }
    }
}

// ===========================================================================
// Kernel 2: 1x1 conv (C->9) + BN + PReLU -> g_kern [N,9,H*W]
// Split-K: 512 threads, 2 threads per pixel (128 ci each), smem combine.
// ===========================================================================
__global__ __launch_bounds__(512)
void conv1x1_bn_prelu(const float* __restrict__ W2,
                      const float* __restrict__ g2,
                      const float* __restrict__ b2,
                      const float* __restrict__ m2,
                      const float* __restrict__ v2,
                      const float* __restrict__ a2)
{
    __shared__ float w2s[K2][CC];
    __shared__ float part[256][K2];
    const int tx   = threadIdx.x;
    const int half = tx >> 8;          // 0 or 1 (ci half)
    const int t    = tx & 255;         // pixel slot
    for (int i = tx; i < K2 * CC; i += 512) {
        int k  = i / CC;
        int ci = i - k * CC;
        w2s[k][ci] = W2[k * CC + ci];
    }
    __syncthreads();

    int pix = blockIdx.x * 256 + t;
    int n   = pix / HW;
    int hw  = pix - n * HW;

    float acc[K2];
#pragma unroll
    for (int k = 0; k < K2; k++) acc[k] = 0.f;

    const int cbase = half * 128;
    const float* hp = g_h + (size_t)n * CC * HW + (size_t)cbase * HW + hw;
#pragma unroll 8
    for (int ci = 0; ci < 128; ci++) {
        float v = hp[(size_t)ci * HW];
#pragma unroll
        for (int k = 0; k < K2; k++)
            acc[k] = fmaf(v, w2s[k][cbase + ci], acc[k]);
    }

    if (half == 1) {
#pragma unroll
        for (int k = 0; k < K2; k++) part[t][k] = acc[k];
    }
    __syncthreads();
    if (half == 0) {
        const float alpha = a2[0];
#pragma unroll
        for (int k = 0; k < K2; k++) {
            float sc = g2[k] * rsqrtf(v2[k] + BN_EPS);
            float sh = b2[k] - m2[k] * sc;
            float v  = (acc[k] + part[t][k]) * sc + sh;
            v = (v >= 0.f) ? v : alpha * v;
            g_kern[((size_t)n * K2 + k) * HW + hw] = v;
        }
    }
}

// ===========================================================================
// Kernel 3: dynamic filter application with torch's ROW-MAJOR reshape scramble
// ===========================================================================
#define G_P 4
#define SLAB 2304
#define SLABP 2305

__global__ __launch_bounds__(256)
void apply_dynamic_kernel(const float* __restrict__ x,
                          float* __restrict__ out)
{
    __shared__ float sA[G_P * SLABP];
    __shared__ float sk[G_P][K2];

    const int tid = threadIdx.x;
    const int P0  = blockIdx.x * G_P;
    const int n   = blockIdx.y;

    if (tid < G_P * K2) {
        int p = tid / K2;
        int k = tid - p * K2;
        sk[p][k] = g_kern[((size_t)n * K2 + k) * HW + P0 + p];
    }

    const float* xn = x + (size_t)n * CC * HW;
    const int base = P0 * SLAB;

    for (int t = tid; t < G_P * SLAB; t += 256) {
        int flat = base + t;
        int w2 = flat & 63;
        int j  = flat >> 6;
        int h2 = j & 63;
        int q  = j >> 6;             // c2*9 + k2
        int k2 = q % 9;
        int c2 = q / 9;
        int r  = k2 / 3;
        int s  = k2 - r * 3;
        int ih = h2 + r - 1;
        int iw = w2 + s - 1;
        float v = 0.f;
        if (ih >= 0 && ih < HH && iw >= 0 && iw < WW)
            v = xn[c2 * HW + ih * WW + iw];
        int slab = t / SLAB;
        int off  = t - slab * SLAB;
        sA[slab * SLABP + off] = v;
    }
    __syncthreads();

    const int c = tid;
    float res[G_P];
#pragma unroll
    for (int p = 0; p < G_P; p++) {
        const float* a = sA + p * SLABP + c * K2;
        float acc = 0.f;
#pragma unroll
        for (int k = 0; k < K2; k++)
            acc = fmaf(a[k], sk[p][k], acc);
        res[p] = acc;
    }

    float* dst = out + ((size_t)n * CC + c) * HW + P0;
#pragma unroll
    for (int p = 0; p < G_P; p++) dst[p] = res[p];
}

// ===========================================================================
extern "C" void kernel_launch(void* const* d_in, const int* in_sizes, int n_in,
                              void* d_out, int out_size)
{
    const float* x  = (const float*)d_in[0];
    const float* y  = (const float*)d_in[1];
    const float* W1 = (const float*)d_in[2];
    const float* g1 = (const float*)d_in[3];
    const float* b1 = (const float*)d_in[4];
    const float* m1 = (const float*)d_in[5];
    const float* v1 = (const float*)d_in[6];
    const float* a1 = (const float*)d_in[7];
    const float* W2 = (const float*)d_in[8];
    const float* g2 = (const float*)d_in[9];
    const float* b2 = (const float*)d_in[10];
    const float* m2 = (const float*)d_in[11];
    const float* v2 = (const float*)d_in[12];
    const float* a2 = (const float*)d_in[13];
    float* out = (float*)d_out;

    static bool attr_set = false;
    if (!attr_set) {
        cudaFuncSetAttribute(conv3x3_mma,
                             cudaFuncAttributeMaxDynamicSharedMemorySize,
                             CONV_SMEM);
        attr_set = true;
    }

    // prep: weight reshape + y transpose to bf16 hi/lo
    prep_weights<<<(K2 * CC * CC + 255) / 256, 256>>>(W1);
    {
        dim3 g(HW / 32, CC / 32, NN);    // (128, 8, 16)
        prep_y_transpose<<<g, 256>>>(y);
    }
    // conv1 on mma.sync tensor cores (bf16 3-MMA, 2 CTAs/SM)
    {
        dim3 g(HW / 128, CC / 128, NN);  // (32, 2, 16) = 1024 CTAs
        conv3x3_mma<<<g, 256, CONV_SMEM>>>(g1, b1, m1, v1, a1);
    }
    // 1x1 conv (split-K, 512 threads)
    conv1x1_bn_prelu<<<(NN * HW) / 256, 512>>>(W2, g2, b2, m2, v2, a2);
    // dynamic filter application
    {
        dim3 g(HW / G_P, NN);            // (1024, 16)
        apply_dynamic_kernel<<<g, 256>>>(x, out);
    }
}

// round 12
// speedup vs baseline: 2.0480x; 1.5693x over previous
#include <cuda_runtime.h>
#include <cuda_fp16.h>
#include <math.h>
#include <stdint.h>

// Problem constants
#define NN 16
#define CC 256
#define HH 64
#define WW 64
#define HW (HH * WW)        // 4096
#define K2 9
#define BN_EPS 1e-5f

// Scratch (device globals; no allocation allowed)
__device__ float g_h[NN * CC * HW];                    // conv1 out (BN+PReLU)
__device__ float g_kern[NN * K2 * HW];                 // dyn kernel [N,9,H*W]
__device__ __align__(16) __half g_wth[K2 * CC * CC];   // W1 fp16 [tap][co][ci]
__device__ __align__(16) __half g_yth[NN * HW * CC];   // y fp16 K-major [n][pix][ci]

// ===========================================================================
// mma.sync / ldmatrix / cp.async helpers (baseline PTX, valid at compute_103)
// ===========================================================================
__device__ __forceinline__ uint32_t smem_u32(const void* p) {
    uint32_t a;
    asm("{ .reg .u64 t; cvta.to.shared.u64 t, %1; cvt.u32.u64 %0, t; }"
        : "=r"(a) : "l"(p));
    return a;
}
__device__ __forceinline__ void ldsm4(uint32_t& r0, uint32_t& r1,
                                      uint32_t& r2, uint32_t& r3, uint32_t addr) {
    asm volatile("ldmatrix.sync.aligned.m8n8.x4.shared.b16 {%0,%1,%2,%3}, [%4];"
                 : "=r"(r0), "=r"(r1), "=r"(r2), "=r"(r3) : "r"(addr));
}
__device__ __forceinline__ void mma_f16(float* c, const uint32_t* a, const uint32_t* b) {
    asm volatile("mma.sync.aligned.m16n8k16.row.col.f32.f16.f16.f32 "
                 "{%0,%1,%2,%3}, {%4,%5,%6,%7}, {%8,%9}, {%0,%1,%2,%3};"
                 : "+f"(c[0]), "+f"(c[1]), "+f"(c[2]), "+f"(c[3])
                 : "r"(a[0]), "r"(a[1]), "r"(a[2]), "r"(a[3]), "r"(b[0]), "r"(b[1]));
}
__device__ __forceinline__ void cp16(uint32_t dst, const void* src, int srcsz) {
    asm volatile("cp.async.cg.shared.global [%0], [%1], 16, %2;"
                 :: "r"(dst), "l"(src), "r"(srcsz) : "memory");
}
#define CP_COMMIT() asm volatile("cp.async.commit_group;" ::: "memory")
#define CP_WAIT1()  asm volatile("cp.async.wait_group 1;" ::: "memory")
#define CP_WAIT0()  asm volatile("cp.async.wait_group 0;" ::: "memory")

// ===========================================================================
// Prep A: W1 [co][ci][3][3] fp32 -> fp16 [tap][co][ci]
// ===========================================================================
__global__ __launch_bounds__(256)
void prep_weights(const float* __restrict__ W1)
{
    int idx = blockIdx.x * 256 + threadIdx.x;     // over 9*256*256
    if (idx >= K2 * CC * CC) return;
    int k   = idx >> 16;
    int rem = idx & 0xFFFF;
    int co  = rem >> 8;
    int ci  = rem & 255;
    g_wth[idx] = __float2half(W1[((size_t)co * CC + ci) * 9 + k]);
}

// ===========================================================================
// Prep B: transpose y [n][ci][p] fp32 -> y fp16 [n][p][ci]
// ===========================================================================
__global__ __launch_bounds__(256)
void prep_y_transpose(const float* __restrict__ y)
{
    __shared__ float s[32][33];
    const int n  = blockIdx.z;
    const int p0 = blockIdx.x * 32;
    const int c0 = blockIdx.y * 32;
    const int tx = threadIdx.x;
    const int j  = tx & 31;
    const int i  = tx >> 5;            // 0..7

#pragma unroll
    for (int it = 0; it < 4; it++) {
        int ci = c0 + i + it * 8;
        s[i + it * 8][j] = y[((size_t)n * CC + ci) * HW + p0 + j];
    }
    __syncthreads();
#pragma unroll
    for (int it = 0; it < 4; it++) {
        int pl = i + it * 8;
        g_yth[((size_t)n * HW + p0 + pl) * CC + c0 + j] = __float2half(s[j][pl]);
    }
}

// ===========================================================================
// Kernel 1: conv3x3 as 9-tap GEMM on mma.sync, SINGLE fp16 MMA, fp32 acc.
// (R10's fp16 regression traced to subnormal W-residuals; the pure fp16
//  path has all-normal operands.)
// CTA tile M=128 co x N=128 pix (2 image rows), 8 warps at 64x32,
// ci chunks of 32 (LDB=80, conflict-free ldmatrix). B staged once per chunk
// as a 4x66 halo region; A double-buffered across taps via cp.async.
// smem = 41600 B, occupancy 2.
// ===========================================================================
#define LDB 80                          // bytes per padded smem row (32 ci)
#define A_BUF (128 * LDB)               // one A buffer (10240)
#define OFF_A 0                         // two buffers: 0, A_BUF
#define OFF_BH (2 * A_BUF)              // 20480
#define EXTR 264                        // 4*66 extended pixel rows
#define CONV_SMEM (OFF_BH + EXTR * LDB) // 41600

__global__ __launch_bounds__(256, 2)
void conv3x3_mma(const float* __restrict__ g1,
                 const float* __restrict__ b1,
                 const float* __restrict__ m1,
                 const float* __restrict__ v1,
                 const float* __restrict__ a1)
{
    extern __shared__ char sb[];
    const uint32_t sb32 = smem_u32(sb);

    const int tid  = threadIdx.x;
    const int wid  = tid >> 5;
    const int lane = tid & 31;
    const int wm   = wid >> 2;          // 0..1  (co 64-block)
    const int wn   = wid & 3;           // 0..3  (pix 32-block)
    const int P0   = blockIdx.x * 128;
    const int hh0  = P0 >> 6;           // first image row of this tile
    const int cob  = blockIdx.y * 128;
    const int n    = blockIdx.z;

    const int quad = lane >> 3;         // 0..3
    const int lrow = lane & 7;

    // ldmatrix lane-address components (fragment mapping verified in R8)
    const int armBase = wm * 64 + lrow + ((quad & 1) << 3);
    const int akAdd   = (quad >> 1) << 3;
    const int bnBase  = wn * 32 + lrow + ((quad >> 1) << 3);
    const int bkAdd   = (quad & 1) << 3;

    float acc[4][4][4];
#pragma unroll
    for (int mt = 0; mt < 4; mt++)
#pragma unroll
        for (int nt = 0; nt < 4; nt++)
#pragma unroll
            for (int i = 0; i < 4; i++) acc[mt][nt][i] = 0.f;

    for (int ci0 = 0; ci0 < CC; ci0 += 32) {
        __syncthreads();   // all compute on previous chunk's B/A done

        // ---- stage extended B region, zeros at image border ---------------
        for (int i = tid; i < EXTR * 4; i += 256) {
            int r = i >> 2, q = i & 3;
            int er = r / 66, ec = r - er * 66;
            int ih = hh0 - 1 + er;
            int iw = ec - 1;
            bool valid = ((unsigned)ih < (unsigned)HH) && ((unsigned)iw < (unsigned)WW);
            size_t srow = valid ? (((size_t)n * HW + (ih << 6) + iw) * CC + ci0 + q * 8)
                                : 0;
            int sz = valid ? 16 : 0;
            cp16(sb32 + OFF_BH + (uint32_t)(r * LDB + q * 16), g_yth + srow, sz);
        }
        // ---- stage A for tap 0 into buffer 0 -------------------------------
        {
            const __half* srcH = g_wth + ((size_t)cob << 8) + ci0;
            for (int i = tid; i < 512; i += 256) {
                int r = i >> 2, q = i & 3;
                cp16(sb32 + OFF_A + (uint32_t)(r * LDB + q * 16),
                     srcH + r * 256 + q * 8, 16);
            }
        }
        CP_COMMIT();

        for (int tap = 0; tap < 9; tap++) {
            __syncthreads();   // protect A buffer (tap+1)&1 from overwrite
            if (tap < 8) {
                const int tn = tap + 1;
                const uint32_t bo = OFF_A + (uint32_t)(tn & 1) * A_BUF;
                const __half* srcH = g_wth + ((size_t)tn << 16) +
                                     ((size_t)cob << 8) + ci0;
                for (int i = tid; i < 512; i += 256) {
                    int r = i >> 2, q = i & 3;
                    cp16(sb32 + bo + (uint32_t)(r * LDB + q * 16),
                         srcH + r * 256 + q * 8, 16);
                }
                CP_COMMIT();
                CP_WAIT1();          // current tap's A (+B on tap 0) complete
            } else {
                CP_WAIT0();
            }
            __syncthreads();

            // extended-row indices for this tap (per lane, per n-tile pair)
            const int dr = tap / 3 - 1;
            const int ds = tap - (tap / 3) * 3 - 1;
            int eb[2];
#pragma unroll
            for (int ntp = 0; ntp < 2; ntp++) {
                int rl = bnBase + ntp * 16;
                eb[ntp] = ((rl >> 6) + dr + 1) * 66 + (rl & 63) + ds + 1;
            }
            const uint32_t abuf = sb32 + OFF_A + (uint32_t)(tap & 1) * A_BUF;

#pragma unroll
            for (int kk = 0; kk < 2; kk++) {
                const int k0 = kk * 16;
                uint32_t ah[4][4], bh[4][2];
#pragma unroll
                for (int mt = 0; mt < 4; mt++) {
                    uint32_t aoff = (uint32_t)((armBase + mt * 16) * LDB +
                                               (k0 + akAdd) * 2);
                    ldsm4(ah[mt][0], ah[mt][1], ah[mt][2], ah[mt][3], abuf + aoff);
                }
#pragma unroll
                for (int ntp = 0; ntp < 2; ntp++) {
                    uint32_t boff = (uint32_t)(eb[ntp] * LDB + (k0 + bkAdd) * 2);
                    ldsm4(bh[2 * ntp][0], bh[2 * ntp][1],
                          bh[2 * ntp + 1][0], bh[2 * ntp + 1][1],
                          sb32 + OFF_BH + boff);
                }
#pragma unroll
                for (int mt = 0; mt < 4; mt++) {
#pragma unroll
                    for (int nt = 0; nt < 4; nt++) {
                        mma_f16(acc[mt][nt], ah[mt], bh[nt]);
                    }
                }
            }
        }
    }

    // ---- epilogue: BN + PReLU, store float2 pairs
    const float alpha = a1[0];
#pragma unroll
    for (int mt = 0; mt < 4; mt++) {
        int r0  = wm * 64 + mt * 16 + (lane >> 2);
        int co0 = cob + r0;
        int co1 = co0 + 8;
        float sc0 = g1[co0] * rsqrtf(v1[co0] + BN_EPS);
        float sh0 = b1[co0] - m1[co0] * sc0;
        float sc1 = g1[co1] * rsqrtf(v1[co1] + BN_EPS);
        float sh1 = b1[co1] - m1[co1] * sc1;
        float* base0 = g_h + ((size_t)n * CC + co0) * HW;
        float* base1 = g_h + ((size_t)n * CC + co1) * HW;
#pragma unroll
        for (int nt = 0; nt < 4; nt++) {
            int col = P0 + wn * 32 + nt * 8 + 2 * (lane & 3);
            float v0 = acc[mt][nt][0] * sc0 + sh0;
            float v1_ = acc[mt][nt][1] * sc0 + sh0;
            float v2 = acc[mt][nt][2] * sc1 + sh1;
            float v3 = acc[mt][nt][3] * sc1 + sh1;
            float2 o0, o1;
            o0.x = (v0 >= 0.f) ? v0 : alpha * v0;
            o0.y = (v1_ >= 0.f) ? v1_ : alpha * v1_;
            o1.x = (v2 >= 0.f) ? v2 : alpha * v2;
            o1.y = (v3 >= 0.f) ? v3 : alpha * v3;
            *(float2*)(base0 + col) = o0;
            *(float2*)(base1 + col) = o1;
        }
    }
}

// ===========================================================================
// Kernel 2: 1x1 conv (C->9) + BN + PReLU -> g_kern [N,9,H*W]
// Split-K: 512 threads, 2 threads per pixel (128 ci each), smem combine.
// ===========================================================================
__global__ __launch_bounds__(512)
void conv1x1_bn_prelu(const float* __restrict__ W2,
                      const float* __restrict__ g2,
                      const float* __restrict__ b2,
                      const float* __restrict__ m2,
                      const float* __restrict__ v2,
                      const float* __restrict__ a2)
{
    __shared__ float w2s[K2][CC];
    __shared__ float part[256][K2];
    const int tx   = threadIdx.x;
    const int half = tx >> 8;          // 0 or 1 (ci half)
    const int t    = tx & 255;         // pixel slot
    for (int i = tx; i < K2 * CC; i += 512) {
        int k  = i / CC;
        int ci = i - k * CC;
        w2s[k][ci] = W2[k * CC + ci];
    }
    __syncthreads();

    int pix = blockIdx.x * 256 + t;
    int n   = pix / HW;
    int hw  = pix - n * HW;

    float acc[K2];
#pragma unroll
    for (int k = 0; k < K2; k++) acc[k] = 0.f;

    const int cbase = half * 128;
    const float* hp = g_h + (size_t)n * CC * HW + (size_t)cbase * HW + hw;
#pragma unroll 8
    for (int ci = 0; ci < 128; ci++) {
        float v = hp[(size_t)ci * HW];
#pragma unroll
        for (int k = 0; k < K2; k++)
            acc[k] = fmaf(v, w2s[k][cbase + ci], acc[k]);
    }

    if (half == 1) {
#pragma unroll
        for (int k = 0; k < K2; k++) part[t][k] = acc[k];
    }
    __syncthreads();
    if (half == 0) {
        const float alpha = a2[0];
#pragma unroll
        for (int k = 0; k < K2; k++) {
            float sc = g2[k] * rsqrtf(v2[k] + BN_EPS);
            float sh = b2[k] - m2[k] * sc;
            float v  = (acc[k] + part[t][k]) * sc + sh;
            v = (v >= 0.f) ? v : alpha * v;
            g_kern[((size_t)n * K2 + k) * HW + hw] = v;
        }
    }
}

// ===========================================================================
// Kernel 3: dynamic filter application with torch's ROW-MAJOR reshape scramble
// ===========================================================================
#define G_P 4
#define SLAB 2304
#define SLABP 2305

__global__ __launch_bounds__(256)
void apply_dynamic_kernel(const float* __restrict__ x,
                          float* __restrict__ out)
{
    __shared__ float sA[G_P * SLABP];
    __shared__ float sk[G_P][K2];

    const int tid = threadIdx.x;
    const int P0  = blockIdx.x * G_P;
    const int n   = blockIdx.y;

    if (tid < G_P * K2) {
        int p = tid / K2;
        int k = tid - p * K2;
        sk[p][k] = g_kern[((size_t)n * K2 + k) * HW + P0 + p];
    }

    const float* xn = x + (size_t)n * CC * HW;
    const int base = P0 * SLAB;

    for (int t = tid; t < G_P * SLAB; t += 256) {
        int flat = base + t;
        int w2 = flat & 63;
        int j  = flat >> 6;
        int h2 = j & 63;
        int q  = j >> 6;             // c2*9 + k2
        int k2 = q % 9;
        int c2 = q / 9;
        int r  = k2 / 3;
        int s  = k2 - r * 3;
        int ih = h2 + r - 1;
        int iw = w2 + s - 1;
        float v = 0.f;
        if (ih >= 0 && ih < HH && iw >= 0 && iw < WW)
            v = xn[c2 * HW + ih * WW + iw];
        int slab = t / SLAB;
        int off  = t - slab * SLAB;
        sA[slab * SLABP + off] = v;
    }
    __syncthreads();

    const int c = tid;
    float res[G_P];
#pragma unroll
    for (int p = 0; p < G_P; p++) {
        const float* a = sA + p * SLABP + c * K2;
        float acc = 0.f;
#pragma unroll
        for (int k = 0; k < K2; k++)
            acc = fmaf(a[k], sk[p][k], acc);
        res[p] = acc;
    }

    float* dst = out + ((size_t)n * CC + c) * HW + P0;
#pragma unroll
    for (int p = 0; p < G_P; p++) dst[p] = res[p];
}

// ===========================================================================
extern "C" void kernel_launch(void* const* d_in, const int* in_sizes, int n_in,
                              void* d_out, int out_size)
{
    const float* x  = (const float*)d_in[0];
    const float* y  = (const float*)d_in[1];
    const float* W1 = (const float*)d_in[2];
    const float* g1 = (const float*)d_in[3];
    const float* b1 = (const float*)d_in[4];
    const float* m1 = (const float*)d_in[5];
    const float* v1 = (const float*)d_in[6];
    const float* a1 = (const float*)d_in[7];
    const float* W2 = (const float*)d_in[8];
    const float* g2 = (const float*)d_in[9];
    const float* b2 = (const float*)d_in[10];
    const float* m2 = (const float*)d_in[11];
    const float* v2 = (const float*)d_in[12];
    const float* a2 = (const float*)d_in[13];
    float* out = (float*)d_out;

    static bool attr_set = false;
    if (!attr_set) {
        cudaFuncSetAttribute(conv3x3_mma,
                             cudaFuncAttributeMaxDynamicSharedMemorySize,
                             CONV_SMEM);
        attr_set = true;
    }

    // prep: weight reshape + y transpose to fp16
    prep_weights<<<(K2 * CC * CC + 255) / 256, 256>>>(W1);
    {
        dim3 g(HW / 32, CC / 32, NN);    // (128, 8, 16)
        prep_y_transpose<<<g, 256>>>(y);
    }
    // conv1 on mma.sync tensor cores (single fp16 MMA, 2 CTAs/SM)
    {
        dim3 g(HW / 128, CC / 128, NN);  // (32, 2, 16) = 1024 CTAs
        conv3x3_mma<<<g, 256, CONV_SMEM>>>(g1, b1, m1, v1, a1);
    }
    // 1x1 conv (split-K, 512 threads)
    conv1x1_bn_prelu<<<(NN * HW) / 256, 512>>>(W2, g2, b2, m2, v2, a2);
    // dynamic filter application
    {
        dim3 g(HW / G_P, NN);            // (1024, 16)
        apply_dynamic_kernel<<<g, 256>>>(x, out);
    }
}

// round 14
// speedup vs baseline: 2.1299x; 1.0400x over previous
#include <cuda_runtime.h>
#include <cuda_fp16.h>
#include <math.h>
#include <stdint.h>

// Problem constants
#define NN 16
#define CC 256
#define HH 64
#define WW 64
#define HW (HH * WW)        // 4096
#define K2 9
#define BN_EPS 1e-5f

// Scratch (device globals; no allocation allowed)
__device__ float g_h[NN * CC * HW];                    // conv1 out (BN+PReLU)
__device__ float g_kern[NN * K2 * HW];                 // dyn kernel [N,9,H*W]
__device__ __align__(16) __half g_wth[K2 * CC * CC];   // W1 fp16 [tap][co][ci]
__device__ __align__(16) __half g_yth[NN * HW * CC];   // y fp16 K-major [n][pix][ci]

// ===========================================================================
// mma.sync / ldmatrix / cp.async helpers (baseline PTX, valid at compute_103)
// ===========================================================================
__device__ __forceinline__ uint32_t smem_u32(const void* p) {
    uint32_t a;
    asm("{ .reg .u64 t; cvta.to.shared.u64 t, %1; cvt.u32.u64 %0, t; }"
        : "=r"(a) : "l"(p));
    return a;
}
__device__ __forceinline__ void ldsm4(uint32_t& r0, uint32_t& r1,
                                      uint32_t& r2, uint32_t& r3, uint32_t addr) {
    asm volatile("ldmatrix.sync.aligned.m8n8.x4.shared.b16 {%0,%1,%2,%3}, [%4];"
                 : "=r"(r0), "=r"(r1), "=r"(r2), "=r"(r3) : "r"(addr));
}
__device__ __forceinline__ void mma_f16(float* c, const uint32_t* a, const uint32_t* b) {
    asm volatile("mma.sync.aligned.m16n8k16.row.col.f32.f16.f16.f32 "
                 "{%0,%1,%2,%3}, {%4,%5,%6,%7}, {%8,%9}, {%0,%1,%2,%3};"
                 : "+f"(c[0]), "+f"(c[1]), "+f"(c[2]), "+f"(c[3])
                 : "r"(a[0]), "r"(a[1]), "r"(a[2]), "r"(a[3]), "r"(b[0]), "r"(b[1]));
}
__device__ __forceinline__ void cp16(uint32_t dst, const void* src, int srcsz) {
    asm volatile("cp.async.cg.shared.global [%0], [%1], 16, %2;"
                 :: "r"(dst), "l"(src), "r"(srcsz) : "memory");
}
#define CP_COMMIT() asm volatile("cp.async.commit_group;" ::: "memory")
#define CP_WAIT1()  asm volatile("cp.async.wait_group 1;" ::: "memory")
#define CP_WAIT0()  asm volatile("cp.async.wait_group 0;" ::: "memory")

// ===========================================================================
// Prep A: W1 [co][ci][3][3] fp32 -> fp16 [tap][co][ci]
// ===========================================================================
__global__ __launch_bounds__(256)
void prep_weights(const float* __restrict__ W1)
{
    int idx = blockIdx.x * 256 + threadIdx.x;     // over 9*256*256
    if (idx >= K2 * CC * CC) return;
    int k   = idx >> 16;
    int rem = idx & 0xFFFF;
    int co  = rem >> 8;
    int ci  = rem & 255;
    g_wth[idx] = __float2half(W1[((size_t)co * CC + ci) * 9 + k]);
}

// ===========================================================================
// Prep B: transpose y [n][ci][p] fp32 -> y fp16 [n][p][ci]
// ===========================================================================
__global__ __launch_bounds__(256)
void prep_y_transpose(const float* __restrict__ y)
{
    __shared__ float s[32][33];
    const int n  = blockIdx.z;
    const int p0 = blockIdx.x * 32;
    const int c0 = blockIdx.y * 32;
    const int tx = threadIdx.x;
    const int j  = tx & 31;
    const int i  = tx >> 5;            // 0..7

#pragma unroll
    for (int it = 0; it < 4; it++) {
        int ci = c0 + i + it * 8;
        s[i + it * 8][j] = y[((size_t)n * CC + ci) * HW + p0 + j];
    }
    __syncthreads();
#pragma unroll
    for (int it = 0; it < 4; it++) {
        int pl = i + it * 8;
        g_yth[((size_t)n * HW + p0 + pl) * CC + c0 + j] = __float2half(s[j][pl]);
    }
}

// ===========================================================================
// Kernel 1: conv3x3 as 9-tap GEMM on mma.sync, single fp16 MMA, fp32 acc.
// CTA tile M=128 co x N=128 pix (2 image rows), 8 warps at 64x32.
// ci chunks of 64 (LDB=144: 8-row ldmatrix groups bank-rotate by 16B ->
// conflict-free). 36 stage+compute iterations (halved vs R12).
// B staged once per chunk as 4x66 halo region; A double-buffered via cp.async.
// smem = 74880 B, occupancy 2.
// ===========================================================================
#define LDB 144                         // bytes per padded smem row (64 ci)
#define A_BUF (128 * LDB)               // one A buffer (18432)
#define OFF_A 0                         // two buffers: 0, A_BUF
#define OFF_BH (2 * A_BUF)              // 36864
#define EXTR 264                        // 4*66 extended pixel rows
#define CONV_SMEM (OFF_BH + EXTR * LDB) // 74880

__global__ __launch_bounds__(256, 2)
void conv3x3_mma(const float* __restrict__ g1,
                 const float* __restrict__ b1,
                 const float* __restrict__ m1,
                 const float* __restrict__ v1,
                 const float* __restrict__ a1)
{
    extern __shared__ char sb[];
    const uint32_t sb32 = smem_u32(sb);

    const int tid  = threadIdx.x;
    const int wid  = tid >> 5;
    const int lane = tid & 31;
    const int wm   = wid >> 2;          // 0..1  (co 64-block)
    const int wn   = wid & 3;           // 0..3  (pix 32-block)
    const int P0   = blockIdx.x * 128;
    const int hh0  = P0 >> 6;           // first image row of this tile
    const int cob  = blockIdx.y * 128;
    const int n    = blockIdx.z;

    const int quad = lane >> 3;         // 0..3
    const int lrow = lane & 7;

    // ldmatrix lane-address components (fragment mapping verified in R8)
    const int armBase = wm * 64 + lrow + ((quad & 1) << 3);
    const int akAdd   = (quad >> 1) << 3;
    const int bnBase  = wn * 32 + lrow + ((quad >> 1) << 3);
    const int bkAdd   = (quad & 1) << 3;

    float acc[4][4][4];
#pragma unroll
    for (int mt = 0; mt < 4; mt++)
#pragma unroll
        for (int nt = 0; nt < 4; nt++)
#pragma unroll
            for (int i = 0; i < 4; i++) acc[mt][nt][i] = 0.f;

    for (int ci0 = 0; ci0 < CC; ci0 += 64) {
        __syncthreads();   // all compute on previous chunk's B/A done

        // ---- stage extended B region, zeros at image border ---------------
        for (int i = tid; i < EXTR * 8; i += 256) {
            int r = i >> 3, q = i & 7;
            int er = r / 66, ec = r - er * 66;
            int ih = hh0 - 1 + er;
            int iw = ec - 1;
            bool valid = ((unsigned)ih < (unsigned)HH) && ((unsigned)iw < (unsigned)WW);
            size_t srow = valid ? (((size_t)n * HW + (ih << 6) + iw) * CC + ci0 + q * 8)
                                : 0;
            int sz = valid ? 16 : 0;
            cp16(sb32 + OFF_BH + (uint32_t)(r * LDB + q * 16), g_yth + srow, sz);
        }
        // ---- stage A for tap 0 into buffer 0 -------------------------------
        {
            const __half* srcH = g_wth + ((size_t)cob << 8) + ci0;
            for (int i = tid; i < 1024; i += 256) {
                int r = i >> 3, q = i & 7;
                cp16(sb32 + OFF_A + (uint32_t)(r * LDB + q * 16),
                     srcH + r * 256 + q * 8, 16);
            }
        }
        CP_COMMIT();

        for (int tap = 0; tap < 9; tap++) {
            __syncthreads();   // protect A buffer (tap+1)&1 from overwrite
            if (tap < 8) {
                const int tn = tap + 1;
                const uint32_t bo = OFF_A + (uint32_t)(tn & 1) * A_BUF;
                const __half* srcH = g_wth + ((size_t)tn << 16) +
                                     ((size_t)cob << 8) + ci0;
                for (int i = tid; i < 1024; i += 256) {
                    int r = i >> 3, q = i & 7;
                    cp16(sb32 + bo + (uint32_t)(r * LDB + q * 16),
                         srcH + r * 256 + q * 8, 16);
                }
                CP_COMMIT();
                CP_WAIT1();          // current tap's A (+B on tap 0) complete
            } else {
                CP_WAIT0();
            }
            __syncthreads();

            // extended-row indices for this tap (per lane, per n-tile pair)
            const int dr = tap / 3 - 1;
            const int ds = tap - (tap / 3) * 3 - 1;
            int eb[2];
#pragma unroll
            for (int ntp = 0; ntp < 2; ntp++) {
                int rl = bnBase + ntp * 16;
                eb[ntp] = ((rl >> 6) + dr + 1) * 66 + (rl & 63) + ds + 1;
            }
            const uint32_t abuf = sb32 + OFF_A + (uint32_t)(tap & 1) * A_BUF;

#pragma unroll
            for (int kk = 0; kk < 4; kk++) {
                const int k0 = kk * 16;
                uint32_t ah[4][4], bh[4][2];
#pragma unroll
                for (int mt = 0; mt < 4; mt++) {
                    uint32_t aoff = (uint32_t)((armBase + mt * 16) * LDB +
                                               (k0 + akAdd) * 2);
                    ldsm4(ah[mt][0], ah[mt][1], ah[mt][2], ah[mt][3], abuf + aoff);
                }
#pragma unroll
                for (int ntp = 0; ntp < 2; ntp++) {
                    uint32_t boff = (uint32_t)(eb[ntp] * LDB + (k0 + bkAdd) * 2);
                    ldsm4(bh[2 * ntp][0], bh[2 * ntp][1],
                          bh[2 * ntp + 1][0], bh[2 * ntp + 1][1],
                          sb32 + OFF_BH + boff);
                }
#pragma unroll
                for (int mt = 0; mt < 4; mt++) {
#pragma unroll
                    for (int nt = 0; nt < 4; nt++) {
                        mma_f16(acc[mt][nt], ah[mt], bh[nt]);
                    }
                }
            }
        }
    }

    // ---- epilogue: BN + PReLU, store float2 pairs
    const float alpha = a1[0];
#pragma unroll
    for (int mt = 0; mt < 4; mt++) {
        int r0  = wm * 64 + mt * 16 + (lane >> 2);
        int co0 = cob + r0;
        int co1 = co0 + 8;
        float sc0 = g1[co0] * rsqrtf(v1[co0] + BN_EPS);
        float sh0 = b1[co0] - m1[co0] * sc0;
        float sc1 = g1[co1] * rsqrtf(v1[co1] + BN_EPS);
        float sh1 = b1[co1] - m1[co1] * sc1;
        float* base0 = g_h + ((size_t)n * CC + co0) * HW;
        float* base1 = g_h + ((size_t)n * CC + co1) * HW;
#pragma unroll
        for (int nt = 0; nt < 4; nt++) {
            int col = P0 + wn * 32 + nt * 8 + 2 * (lane & 3);
            float v0 = acc[mt][nt][0] * sc0 + sh0;
            float v1_ = acc[mt][nt][1] * sc0 + sh0;
            float v2 = acc[mt][nt][2] * sc1 + sh1;
            float v3 = acc[mt][nt][3] * sc1 + sh1;
            float2 o0, o1;
            o0.x = (v0 >= 0.f) ? v0 : alpha * v0;
            o0.y = (v1_ >= 0.f) ? v1_ : alpha * v1_;
            o1.x = (v2 >= 0.f) ? v2 : alpha * v2;
            o1.y = (v3 >= 0.f) ? v3 : alpha * v3;
            *(float2*)(base0 + col) = o0;
            *(float2*)(base1 + col) = o1;
        }
    }
}

// ===========================================================================
// Kernel 2: 1x1 conv (C->9) + BN + PReLU -> g_kern [N,9,H*W]
// Split-K: 512 threads, 2 threads per pixel (128 ci each), smem combine.
// ===========================================================================
__global__ __launch_bounds__(512)
void conv1x1_bn_prelu(const float* __restrict__ W2,
                      const float* __restrict__ g2,
                      const float* __restrict__ b2,
                      const float* __restrict__ m2,
                      const float* __restrict__ v2,
                      const float* __restrict__ a2)
{
    __shared__ float w2s[K2][CC];
    __shared__ float part[256][K2];
    const int tx   = threadIdx.x;
    const int half = tx >> 8;          // 0 or 1 (ci half)
    const int t    = tx & 255;         // pixel slot
    for (int i = tx; i < K2 * CC; i += 512) {
        int k  = i / CC;
        int ci = i - k * CC;
        w2s[k][ci] = W2[k * CC + ci];
    }
    __syncthreads();

    int pix = blockIdx.x * 256 + t;
    int n   = pix / HW;
    int hw  = pix - n * HW;

    float acc[K2];
#pragma unroll
    for (int k = 0; k < K2; k++) acc[k] = 0.f;

    const int cbase = half * 128;
    const float* hp = g_h + (size_t)n * CC * HW + (size_t)cbase * HW + hw;
#pragma unroll 8
    for (int ci = 0; ci < 128; ci++) {
        float v = hp[(size_t)ci * HW];
#pragma unroll
        for (int k = 0; k < K2; k++)
            acc[k] = fmaf(v, w2s[k][cbase + ci], acc[k]);
    }

    if (half == 1) {
#pragma unroll
        for (int k = 0; k < K2; k++) part[t][k] = acc[k];
    }
    __syncthreads();
    if (half == 0) {
        const float alpha = a2[0];
#pragma unroll
        for (int k = 0; k < K2; k++) {
            float sc = g2[k] * rsqrtf(v2[k] + BN_EPS);
            float sh = b2[k] - m2[k] * sc;
            float v  = (acc[k] + part[t][k]) * sc + sh;
            v = (v >= 0.f) ? v : alpha * v;
            g_kern[((size_t)n * K2 + k) * HW + hw] = v;
        }
    }
}

// ===========================================================================
// Kernel 3: dynamic filter application with torch's ROW-MAJOR reshape scramble
// ===========================================================================
#define G_P 4
#define SLAB 2304
#define SLABP 2305

__global__ __launch_bounds__(256)
void apply_dynamic_kernel(const float* __restrict__ x,
                          float* __restrict__ out)
{
    __shared__ float sA[G_P * SLABP];
    __shared__ float sk[G_P][K2];

    const int tid = threadIdx.x;
    const int P0  = blockIdx.x * G_P;
    const int n   = blockIdx.y;

    if (tid < G_P * K2) {
        int p = tid / K2;
        int k = tid - p * K2;
        sk[p][k] = g_kern[((size_t)n * K2 + k) * HW + P0 + p];
    }

    const float* xn = x + (size_t)n * CC * HW;
    const int base = P0 * SLAB;

    for (int t = tid; t < G_P * SLAB; t += 256) {
        int flat = base + t;
        int w2 = flat & 63;
        int j  = flat >> 6;
        int h2 = j & 63;
        int q  = j >> 6;             // c2*9 + k2
        int k2 = q % 9;
        int c2 = q / 9;
        int r  = k2 / 3;
        int s  = k2 - r * 3;
        int ih = h2 + r - 1;
        int iw = w2 + s - 1;
        float v = 0.f;
        if (ih >= 0 && ih < HH && iw >= 0 && iw < WW)
            v = xn[c2 * HW + ih * WW + iw];
        int slab = t / SLAB;
        int off  = t - slab * SLAB;
        sA[slab * SLABP + off] = v;
    }
    __syncthreads();

    const int c = tid;
    float res[G_P];
#pragma unroll
    for (int p = 0; p < G_P; p++) {
        const float* a = sA + p * SLABP + c * K2;
        float acc = 0.f;
#pragma unroll
        for (int k = 0; k < K2; k++)
            acc = fmaf(a[k], sk[p][k], acc);
        res[p] = acc;
    }

    float* dst = out + ((size_t)n * CC + c) * HW + P0;
#pragma unroll
    for (int p = 0; p < G_P; p++) dst[p] = res[p];
}

// ===========================================================================
extern "C" void kernel_launch(void* const* d_in, const int* in_sizes, int n_in,
                              void* d_out, int out_size)
{
    const float* x  = (const float*)d_in[0];
    const float* y  = (const float*)d_in[1];
    const float* W1 = (const float*)d_in[2];
    const float* g1 = (const float*)d_in[3];
    const float* b1 = (const float*)d_in[4];
    const float* m1 = (const float*)d_in[5];
    const float* v1 = (const float*)d_in[6];
    const float* a1 = (const float*)d_in[7];
    const float* W2 = (const float*)d_in[8];
    const float* g2 = (const float*)d_in[9];
    const float* b2 = (const float*)d_in[10];
    const float* m2 = (const float*)d_in[11];
    const float* v2 = (const float*)d_in[12];
    const float* a2 = (const float*)d_in[13];
    float* out = (float*)d_out;

    static bool attr_set = false;
    if (!attr_set) {
        cudaFuncSetAttribute(conv3x3_mma,
                             cudaFuncAttributeMaxDynamicSharedMemorySize,
                             CONV_SMEM);
        attr_set = true;
    }

    // prep: weight reshape + y transpose to fp16
    prep_weights<<<(K2 * CC * CC + 255) / 256, 256>>>(W1);
    {
        dim3 g(HW / 32, CC / 32, NN);    // (128, 8, 16)
        prep_y_transpose<<<g, 256>>>(y);
    }
    // conv1 on mma.sync tensor cores (single fp16 MMA, ci-chunk 64, 2 CTAs/SM)
    {
        dim3 g(HW / 128, CC / 128, NN);  // (32, 2, 16) = 1024 CTAs
        conv3x3_mma<<<g, 256, CONV_SMEM>>>(g1, b1, m1, v1, a1);
    }
    // 1x1 conv (split-K, 512 threads)
    conv1x1_bn_prelu<<<(NN * HW) / 256, 512>>>(W2, g2, b2, m2, v2, a2);
    // dynamic filter application
    {
        dim3 g(HW / G_P, NN);            // (1024, 16)
        apply_dynamic_kernel<<<g, 256>>>(x, out);
    }
}

// round 15
// speedup vs baseline: 2.1398x; 1.0047x over previous
#include <cuda_runtime.h>
#include <cuda_fp16.h>
#include <math.h>
#include <stdint.h>

// Problem constants
#define NN 16
#define CC 256
#define HH 64
#define WW 64
#define HW (HH * WW)        // 4096
#define K2 9
#define BN_EPS 1e-5f

// Scratch (device globals; no allocation allowed)
__device__ float g_h[NN * CC * HW];                    // conv1 out (BN+PReLU)
__device__ float g_kern[NN * K2 * HW];                 // dyn kernel [N,9,H*W]
__device__ __align__(16) __half g_wth[K2 * CC * CC];   // W1 fp16 [tap][co][ci]
__device__ __align__(16) __half g_yth[NN * HW * CC];   // y fp16 K-major [n][pix][ci]

// ===========================================================================
// mma.sync / ldmatrix / cp.async helpers (baseline PTX, valid at compute_103)
// ===========================================================================
__device__ __forceinline__ uint32_t smem_u32(const void* p) {
    uint32_t a;
    asm("{ .reg .u64 t; cvta.to.shared.u64 t, %1; cvt.u32.u64 %0, t; }"
        : "=r"(a) : "l"(p));
    return a;
}
__device__ __forceinline__ void ldsm4(uint32_t& r0, uint32_t& r1,
                                      uint32_t& r2, uint32_t& r3, uint32_t addr) {
    asm volatile("ldmatrix.sync.aligned.m8n8.x4.shared.b16 {%0,%1,%2,%3}, [%4];"
                 : "=r"(r0), "=r"(r1), "=r"(r2), "=r"(r3) : "r"(addr));
}
__device__ __forceinline__ void mma_f16(float* c, const uint32_t* a, const uint32_t* b) {
    asm volatile("mma.sync.aligned.m16n8k16.row.col.f32.f16.f16.f32 "
                 "{%0,%1,%2,%3}, {%4,%5,%6,%7}, {%8,%9}, {%0,%1,%2,%3};"
                 : "+f"(c[0]), "+f"(c[1]), "+f"(c[2]), "+f"(c[3])
                 : "r"(a[0]), "r"(a[1]), "r"(a[2]), "r"(a[3]), "r"(b[0]), "r"(b[1]));
}
__device__ __forceinline__ void cp16(uint32_t dst, const void* src, int srcsz) {
    asm volatile("cp.async.cg.shared.global [%0], [%1], 16, %2;"
                 :: "r"(dst), "l"(src), "r"(srcsz) : "memory");
}
__device__ __forceinline__ void cp4(uint32_t dst, const void* src, int srcsz) {
    asm volatile("cp.async.ca.shared.global [%0], [%1], 4, %2;"
                 :: "r"(dst), "l"(src), "r"(srcsz) : "memory");
}
#define CP_COMMIT() asm volatile("cp.async.commit_group;" ::: "memory")
#define CP_WAIT1()  asm volatile("cp.async.wait_group 1;" ::: "memory")
#define CP_WAIT0()  asm volatile("cp.async.wait_group 0;" ::: "memory")

// ===========================================================================
// Prep A: W1 [co][ci][3][3] fp32 -> fp16 [tap][co][ci]
// ===========================================================================
__global__ __launch_bounds__(256)
void prep_weights(const float* __restrict__ W1)
{
    int idx = blockIdx.x * 256 + threadIdx.x;     // over 9*256*256
    if (idx >= K2 * CC * CC) return;
    int k   = idx >> 16;
    int rem = idx & 0xFFFF;
    int co  = rem >> 8;
    int ci  = rem & 255;
    g_wth[idx] = __float2half(W1[((size_t)co * CC + ci) * 9 + k]);
}

// ===========================================================================
// Prep B: transpose y [n][ci][p] fp32 -> y fp16 [n][p][ci]
// ===========================================================================
__global__ __launch_bounds__(256)
void prep_y_transpose(const float* __restrict__ y)
{
    __shared__ float s[32][33];
    const int n  = blockIdx.z;
    const int p0 = blockIdx.x * 32;
    const int c0 = blockIdx.y * 32;
    const int tx = threadIdx.x;
    const int j  = tx & 31;
    const int i  = tx >> 5;            // 0..7

#pragma unroll
    for (int it = 0; it < 4; it++) {
        int ci = c0 + i + it * 8;
        s[i + it * 8][j] = y[((size_t)n * CC + ci) * HW + p0 + j];
    }
    __syncthreads();
#pragma unroll
    for (int it = 0; it < 4; it++) {
        int pl = i + it * 8;
        g_yth[((size_t)n * HW + p0 + pl) * CC + c0 + j] = __float2half(s[j][pl]);
    }
}

// ===========================================================================
// Kernel 1: conv3x3 as 9-tap GEMM on mma.sync, single fp16 MMA, fp32 acc.
// CTA tile M=128 co x N=128 pix (2 image rows), 8 warps at 64x32.
// ci chunks of 64 (LDB=144, conflict-free ldmatrix). 36 stage+compute iters.
// B staged once per chunk as 4x66 halo region; A double-buffered via cp.async.
// smem = 74880 B, occupancy 2. (Floor-bound on the legacy HMMA pipe.)
// ===========================================================================
#define LDB 144                         // bytes per padded smem row (64 ci)
#define A_BUF (128 * LDB)               // one A buffer (18432)
#define OFF_A 0                         // two buffers: 0, A_BUF
#define OFF_BH (2 * A_BUF)              // 36864
#define EXTR 264                        // 4*66 extended pixel rows
#define CONV_SMEM (OFF_BH + EXTR * LDB) // 74880

__global__ __launch_bounds__(256, 2)
void conv3x3_mma(const float* __restrict__ g1,
                 const float* __restrict__ b1,
                 const float* __restrict__ m1,
                 const float* __restrict__ v1,
                 const float* __restrict__ a1)
{
    extern __shared__ char sb[];
    const uint32_t sb32 = smem_u32(sb);

    const int tid  = threadIdx.x;
    const int wid  = tid >> 5;
    const int lane = tid & 31;
    const int wm   = wid >> 2;          // 0..1  (co 64-block)
    const int wn   = wid & 3;           // 0..3  (pix 32-block)
    const int P0   = blockIdx.x * 128;
    const int hh0  = P0 >> 6;           // first image row of this tile
    const int cob  = blockIdx.y * 128;
    const int n    = blockIdx.z;

    const int quad = lane >> 3;         // 0..3
    const int lrow = lane & 7;

    // ldmatrix lane-address components (fragment mapping verified in R8)
    const int armBase = wm * 64 + lrow + ((quad & 1) << 3);
    const int akAdd   = (quad >> 1) << 3;
    const int bnBase  = wn * 32 + lrow + ((quad >> 1) << 3);
    const int bkAdd   = (quad & 1) << 3;

    float acc[4][4][4];
#pragma unroll
    for (int mt = 0; mt < 4; mt++)
#pragma unroll
        for (int nt = 0; nt < 4; nt++)
#pragma unroll
            for (int i = 0; i < 4; i++) acc[mt][nt][i] = 0.f;

    for (int ci0 = 0; ci0 < CC; ci0 += 64) {
        __syncthreads();   // all compute on previous chunk's B/A done

        // ---- stage extended B region, zeros at image border ---------------
        for (int i = tid; i < EXTR * 8; i += 256) {
            int r = i >> 3, q = i & 7;
            int er = r / 66, ec = r - er * 66;
            int ih = hh0 - 1 + er;
            int iw = ec - 1;
            bool valid = ((unsigned)ih < (unsigned)HH) && ((unsigned)iw < (unsigned)WW);
            size_t srow = valid ? (((size_t)n * HW + (ih << 6) + iw) * CC + ci0 + q * 8)
                                : 0;
            int sz = valid ? 16 : 0;
            cp16(sb32 + OFF_BH + (uint32_t)(r * LDB + q * 16), g_yth + srow, sz);
        }
        // ---- stage A for tap 0 into buffer 0 -------------------------------
        {
            const __half* srcH = g_wth + ((size_t)cob << 8) + ci0;
            for (int i = tid; i < 1024; i += 256) {
                int r = i >> 3, q = i & 7;
                cp16(sb32 + OFF_A + (uint32_t)(r * LDB + q * 16),
                     srcH + r * 256 + q * 8, 16);
            }
        }
        CP_COMMIT();

        for (int tap = 0; tap < 9; tap++) {
            __syncthreads();   // protect A buffer (tap+1)&1 from overwrite
            if (tap < 8) {
                const int tn = tap + 1;
                const uint32_t bo = OFF_A + (uint32_t)(tn & 1) * A_BUF;
                const __half* srcH = g_wth + ((size_t)tn << 16) +
                                     ((size_t)cob << 8) + ci0;
                for (int i = tid; i < 1024; i += 256) {
                    int r = i >> 3, q = i & 7;
                    cp16(sb32 + bo + (uint32_t)(r * LDB + q * 16),
                         srcH + r * 256 + q * 8, 16);
                }
                CP_COMMIT();
                CP_WAIT1();          // current tap's A (+B on tap 0) complete
            } else {
                CP_WAIT0();
            }
            __syncthreads();

            // extended-row indices for this tap (per lane, per n-tile pair)
            const int dr = tap / 3 - 1;
            const int ds = tap - (tap / 3) * 3 - 1;
            int eb[2];
#pragma unroll
            for (int ntp = 0; ntp < 2; ntp++) {
                int rl = bnBase + ntp * 16;
                eb[ntp] = ((rl >> 6) + dr + 1) * 66 + (rl & 63) + ds + 1;
            }
            const uint32_t abuf = sb32 + OFF_A + (uint32_t)(tap & 1) * A_BUF;

#pragma unroll
            for (int kk = 0; kk < 4; kk++) {
                const int k0 = kk * 16;
                uint32_t ah[4][4], bh[4][2];
#pragma unroll
                for (int mt = 0; mt < 4; mt++) {
                    uint32_t aoff = (uint32_t)((armBase + mt * 16) * LDB +
                                               (k0 + akAdd) * 2);
                    ldsm4(ah[mt][0], ah[mt][1], ah[mt][2], ah[mt][3], abuf + aoff);
                }
#pragma unroll
                for (int ntp = 0; ntp < 2; ntp++) {
                    uint32_t boff = (uint32_t)(eb[ntp] * LDB + (k0 + bkAdd) * 2);
                    ldsm4(bh[2 * ntp][0], bh[2 * ntp][1],
                          bh[2 * ntp + 1][0], bh[2 * ntp + 1][1],
                          sb32 + OFF_BH + boff);
                }
#pragma unroll
                for (int mt = 0; mt < 4; mt++) {
#pragma unroll
                    for (int nt = 0; nt < 4; nt++) {
                        mma_f16(acc[mt][nt], ah[mt], bh[nt]);
                    }
                }
            }
        }
    }

    // ---- epilogue: BN + PReLU, store float2 pairs
    const float alpha = a1[0];
#pragma unroll
    for (int mt = 0; mt < 4; mt++) {
        int r0  = wm * 64 + mt * 16 + (lane >> 2);
        int co0 = cob + r0;
        int co1 = co0 + 8;
        float sc0 = g1[co0] * rsqrtf(v1[co0] + BN_EPS);
        float sh0 = b1[co0] - m1[co0] * sc0;
        float sc1 = g1[co1] * rsqrtf(v1[co1] + BN_EPS);
        float sh1 = b1[co1] - m1[co1] * sc1;
        float* base0 = g_h + ((size_t)n * CC + co0) * HW;
        float* base1 = g_h + ((size_t)n * CC + co1) * HW;
#pragma unroll
        for (int nt = 0; nt < 4; nt++) {
            int col = P0 + wn * 32 + nt * 8 + 2 * (lane & 3);
            float v0 = acc[mt][nt][0] * sc0 + sh0;
            float v1_ = acc[mt][nt][1] * sc0 + sh0;
            float v2 = acc[mt][nt][2] * sc1 + sh1;
            float v3 = acc[mt][nt][3] * sc1 + sh1;
            float2 o0, o1;
            o0.x = (v0 >= 0.f) ? v0 : alpha * v0;
            o0.y = (v1_ >= 0.f) ? v1_ : alpha * v1_;
            o1.x = (v2 >= 0.f) ? v2 : alpha * v2;
            o1.y = (v3 >= 0.f) ? v3 : alpha * v3;
            *(float2*)(base0 + col) = o0;
            *(float2*)(base1 + col) = o1;
        }
    }
}

// ===========================================================================
// Kernel 2: 1x1 conv (C->9) + BN + PReLU -> g_kern [N,9,H*W]
// float4 per thread (4 pixels), split-K x2 halves, smem combine.
// 256 threads = 128 pixel-groups x 2 halves; block covers 512 pixels.
// ===========================================================================
__global__ __launch_bounds__(256)
void conv1x1_bn_prelu(const float* __restrict__ W2,
                      const float* __restrict__ g2,
                      const float* __restrict__ b2,
                      const float* __restrict__ m2,
                      const float* __restrict__ v2,
                      const float* __restrict__ a2)
{
    __shared__ float w2s[K2][CC];
    __shared__ float part[128][K2][4];
    const int tx   = threadIdx.x;
    const int half = tx >> 7;          // 0 or 1 (ci half)
    const int t    = tx & 127;         // pixel-group slot
    for (int i = tx; i < K2 * CC; i += 256) {
        int k  = i / CC;
        int ci = i - k * CC;
        w2s[k][ci] = W2[k * CC + ci];
    }
    __syncthreads();

    int g   = blockIdx.x * 128 + t;    // 0 .. 16383 float4 groups
    int hw4 = g << 2;
    int n   = hw4 >> 12;               // /4096
    int hw  = hw4 & 4095;

    float acc[K2][4];
#pragma unroll
    for (int k = 0; k < K2; k++)
#pragma unroll
        for (int p = 0; p < 4; p++) acc[k][p] = 0.f;

    const int cbase = half * 128;
    const float* hp = g_h + ((size_t)n * CC + cbase) * HW + hw;
#pragma unroll 4
    for (int ci = 0; ci < 128; ci++) {
        float4 v = *(const float4*)(hp + (size_t)ci * HW);
#pragma unroll
        for (int k = 0; k < K2; k++) {
            float w = w2s[k][cbase + ci];
            acc[k][0] = fmaf(v.x, w, acc[k][0]);
            acc[k][1] = fmaf(v.y, w, acc[k][1]);
            acc[k][2] = fmaf(v.z, w, acc[k][2]);
            acc[k][3] = fmaf(v.w, w, acc[k][3]);
        }
    }

    if (half == 1) {
#pragma unroll
        for (int k = 0; k < K2; k++)
#pragma unroll
            for (int p = 0; p < 4; p++) part[t][k][p] = acc[k][p];
    }
    __syncthreads();
    if (half == 0) {
        const float alpha = a2[0];
#pragma unroll
        for (int k = 0; k < K2; k++) {
            float sc = g2[k] * rsqrtf(v2[k] + BN_EPS);
            float sh = b2[k] - m2[k] * sc;
            float4 o;
            float r0 = (acc[k][0] + part[t][k][0]) * sc + sh;
            float r1 = (acc[k][1] + part[t][k][1]) * sc + sh;
            float r2 = (acc[k][2] + part[t][k][2]) * sc + sh;
            float r3 = (acc[k][3] + part[t][k][3]) * sc + sh;
            o.x = (r0 >= 0.f) ? r0 : alpha * r0;
            o.y = (r1 >= 0.f) ? r1 : alpha * r1;
            o.z = (r2 >= 0.f) ? r2 : alpha * r2;
            o.w = (r3 >= 0.f) ? r3 : alpha * r3;
            *(float4*)(g_kern + ((size_t)n * K2 + k) * HW + hw) = o;
        }
    }
}

// ===========================================================================
// Kernel 3: dynamic filter application with torch's ROW-MAJOR reshape scramble.
// Staging now uses per-element cp.async (4B, srcsz 0 for border zeros):
// all 36 per-thread copies in flight, no LDG->STS register round-trip.
// ===========================================================================
#define G_P 4
#define SLAB 2304
#define SLABP 2305

__global__ __launch_bounds__(256)
void apply_dynamic_kernel(const float* __restrict__ x,
                          float* __restrict__ out)
{
    __shared__ float sA[G_P * SLABP];
    __shared__ float sk[G_P][K2];

    const int tid = threadIdx.x;
    const int P0  = blockIdx.x * G_P;
    const int n   = blockIdx.y;

    if (tid < G_P * K2) {
        int p = tid / K2;
        int k = tid - p * K2;
        sk[p][k] = g_kern[((size_t)n * K2 + k) * HW + P0 + p];
    }

    const float* xn = x + (size_t)n * CC * HW;
    const int base = P0 * SLAB;
    const uint32_t sA32 = smem_u32(sA);

    for (int t = tid; t < G_P * SLAB; t += 256) {
        int flat = base + t;
        int w2 = flat & 63;
        int j  = flat >> 6;
        int h2 = j & 63;
        int q  = j >> 6;             // c2*9 + k2
        int k2 = q % 9;
        int c2 = q / 9;
        int r  = k2 / 3;
        int s  = k2 - r * 3;
        int ih = h2 + r - 1;
        int iw = w2 + s - 1;
        bool valid = ((unsigned)ih < (unsigned)HH) && ((unsigned)iw < (unsigned)WW);
        const float* src = valid ? (xn + c2 * HW + (ih << 6) + iw) : xn;
        int slab = t / SLAB;
        int off  = t - slab * SLAB;
        cp4(sA32 + (uint32_t)(slab * SLABP + off) * 4, src, valid ? 4 : 0);
    }
    CP_COMMIT();
    CP_WAIT0();
    __syncthreads();

    const int c = tid;
    float res[G_P];
#pragma unroll
    for (int p = 0; p < G_P; p++) {
        const float* a = sA + p * SLABP + c * K2;
        float acc = 0.f;
#pragma unroll
        for (int k = 0; k < K2; k++)
            acc = fmaf(a[k], sk[p][k], acc);
        res[p] = acc;
    }

    float* dst = out + ((size_t)n * CC + c) * HW + P0;
#pragma unroll
    for (int p = 0; p < G_P; p++) dst[p] = res[p];
}

// ===========================================================================
extern "C" void kernel_launch(void* const* d_in, const int* in_sizes, int n_in,
                              void* d_out, int out_size)
{
    const float* x  = (const float*)d_in[0];
    const float* y  = (const float*)d_in[1];
    const float* W1 = (const float*)d_in[2];
    const float* g1 = (const float*)d_in[3];
    const float* b1 = (const float*)d_in[4];
    const float* m1 = (const float*)d_in[5];
    const float* v1 = (const float*)d_in[6];
    const float* a1 = (const float*)d_in[7];
    const float* W2 = (const float*)d_in[8];
    const float* g2 = (const float*)d_in[9];
    const float* b2 = (const float*)d_in[10];
    const float* m2 = (const float*)d_in[11];
    const float* v2 = (const float*)d_in[12];
    const float* a2 = (const float*)d_in[13];
    float* out = (float*)d_out;

    static bool attr_set = false;
    if (!attr_set) {
        cudaFuncSetAttribute(conv3x3_mma,
                             cudaFuncAttributeMaxDynamicSharedMemorySize,
                             CONV_SMEM);
        attr_set = true;
    }

    // prep: weight reshape + y transpose to fp16
    prep_weights<<<(K2 * CC * CC + 255) / 256, 256>>>(W1);
    {
        dim3 g(HW / 32, CC / 32, NN);    // (128, 8, 16)
        prep_y_transpose<<<g, 256>>>(y);
    }
    // conv1 on mma.sync tensor cores (single fp16 MMA, ci-chunk 64, 2 CTAs/SM)
    {
        dim3 g(HW / 128, CC / 128, NN);  // (32, 2, 16) = 1024 CTAs
        conv3x3_mma<<<g, 256, CONV_SMEM>>>(g1, b1, m1, v1, a1);
    }
    // 1x1 conv (float4 pixels, split-K)
    conv1x1_bn_prelu<<<(NN * HW) / 512, 256>>>(W2, g2, b2, m2, v2, a2);
    // dynamic filter application (cp.async staging)
    {
        dim3 g(HW / G_P, NN);            // (1024, 16)
        apply_dynamic_kernel<<<g, 256>>>(x, out);
    }
}